// round 6
// baseline (speedup 1.0000x reference)
#include <cuda_runtime.h>
#include <math.h>

// Problem constants (fixed by the dataset)
#define NB 2
#define NN 50000
#define NF 64
#define NH 32
#define FH 96              // F + H
#define T2 (NB * NN)       // 100000 task rows
#define BNH (NB * NN * NH) // 3,200,000 elements per output tensor
#define EMAX 1000000       // adjacency capacity (dataset E = 800000)

// Scratch: static __device__ arrays (no runtime allocation allowed)
__device__ int    g_is64;           // 1 if edge_index is int64, 0 if int32
__device__ int    g_deg[NN];        // edge-only in-degree (no self loop)
__device__ int    g_off[NN + 1];    // CSR offsets
__device__ int    g_cur[NN];        // CSR fill cursors
__device__ int    g_adj[EMAX];      // CSR: source node per incoming edge
__device__ float  g_dinv[NN];       // rsqrt(deg+1)
__device__ float4 g_y[NN * 48];     // per node: 48 float4 = [b=0: 24][b=1: 24]
__device__ float4 g_vec[NN * 48];   // finished GEMM input (dinv*(sum+self))

// ---------------------------------------------------------------------------
__device__ __forceinline__ int load_idx(const void* ei, long long pos, int is64) {
    if (is64) return (int)((const long long*)ei)[pos];
    return ((const int*)ei)[pos];
}

// K_detect: decide int64 vs int32 from the first 256 values.
__global__ void k_detect(const void* ei) {
    int t = threadIdx.x;
    if (t == 0) g_is64 = 1;
    __syncthreads();
    long long v = ((const long long*)ei)[t];
    if (v < 0 || v >= NN) atomicAnd(&g_is64, 0);
}

// K_zero: deg = 0
__global__ void k_zero() {
    int n = blockIdx.x * blockDim.x + threadIdx.x;
    if (n < NN) g_deg[n] = 0;
}

// K_deg: count edge targets
__global__ void k_deg(const void* __restrict__ ei, int E) {
    int e = blockIdx.x * blockDim.x + threadIdx.x;
    if (e >= E) return;
    int d = load_idx(ei, (long long)E + e, g_is64);
    if ((unsigned)d < NN) atomicAdd(&g_deg[d], 1);
}

// K_scan: exclusive prefix sum over deg -> offsets/cursors, plus dinv.
// Single block of 1024 threads; each handles a contiguous chunk.
__global__ void k_scan() {
    __shared__ int ssum[1024];
    int tid = threadIdx.x;
    const int per = (NN + 1023) / 1024;
    int base = tid * per;
    int s = 0;
    for (int j = 0; j < per; j++) {
        int n = base + j;
        if (n < NN) s += g_deg[n];
    }
    ssum[tid] = s;
    __syncthreads();
    for (int d = 1; d < 1024; d <<= 1) {
        int v = (tid >= d) ? ssum[tid - d] : 0;
        __syncthreads();
        ssum[tid] += v;
        __syncthreads();
    }
    int run = ssum[tid] - s;  // exclusive prefix of this chunk
    for (int j = 0; j < per; j++) {
        int n = base + j;
        if (n < NN) {
            int dg = g_deg[n];
            g_off[n] = run;
            g_cur[n] = run;
            g_dinv[n] = rsqrtf((float)(dg + 1));
            run += dg;
        }
    }
    if (tid == 1023) g_off[NN] = run;
}

// K_scale: y[n][b][:] = dinv[n] * concat(x[b][n], h[b][n])
__global__ void k_scale(const float4* __restrict__ x4, const float4* __restrict__ h4) {
    int i = blockIdx.x * blockDim.x + threadIdx.x;  // over NN*48 float4s
    if (i >= NN * 48) return;
    int n  = i / 48;
    int r  = i % 48;
    int b  = r / 24;
    int k4 = r % 24;
    float4 v;
    if (k4 < 16) v = x4[(b * NN + n) * 16 + k4];
    else         v = h4[(b * NN + n) * 8 + (k4 - 16)];
    float s = g_dinv[n];
    v.x *= s; v.y *= s; v.z *= s; v.w *= s;
    g_y[i] = v;
}

// K_fill: scatter edge sources into CSR slots (cheap int atomics)
__global__ void k_fill(const void* __restrict__ ei, int E) {
    int e = blockIdx.x * blockDim.x + threadIdx.x;
    if (e >= E) return;
    int is64 = g_is64;
    int s = load_idx(ei, e, is64);
    int d = load_idx(ei, (long long)E + e, is64);
    if ((unsigned)s >= NN || (unsigned)d >= NN) return;
    int pos = atomicAdd(&g_cur[d], 1);
    if (pos < EMAX) g_adj[pos] = s;
}

// ---------------------------------------------------------------------------
// K_gather: per node, HALF-WARP accumulates all incoming neighbors in
// registers (3 float4/lane = 192 floats per node, both batches), adds self,
// scales by dinv, writes the finished GEMM input. No float atomics.
__global__ void k_gather() {
    int g    = blockIdx.x * blockDim.x + threadIdx.x;
    int node = g >> 4;
    int lane = g & 15;
    if (node >= NN) return;
    const float4* ys = g_y + (long long)node * 48;
    float4 a0 = ys[lane];
    float4 a1 = ys[lane + 16];
    float4 a2 = ys[lane + 32];
    int beg = g_off[node], end = g_off[node + 1];
    for (int p = beg; p < end; p++) {
        int s = g_adj[p];
        const float4* yv = g_y + (long long)s * 48;
        float4 v0 = yv[lane], v1 = yv[lane + 16], v2 = yv[lane + 32];
        a0.x += v0.x; a0.y += v0.y; a0.z += v0.z; a0.w += v0.w;
        a1.x += v1.x; a1.y += v1.y; a1.z += v1.z; a1.w += v1.w;
        a2.x += v2.x; a2.y += v2.y; a2.z += v2.z; a2.w += v2.w;
    }
    float dv = g_dinv[node];
    a0.x *= dv; a0.y *= dv; a0.z *= dv; a0.w *= dv;
    a1.x *= dv; a1.y *= dv; a1.z *= dv; a1.w *= dv;
    a2.x *= dv; a2.y *= dv; a2.z *= dv; a2.w *= dv;
    float4* out = g_vec + (long long)node * 48;
    out[lane]      = a0;
    out[lane + 16] = a1;
    out[lane + 32] = a2;
}

// ---------------------------------------------------------------------------
// K_final: conv = vec@W + b; LSTM gates; store h,c.
// W is stored in smem gate-interleaved: smem col' = h*4 + gate, so thread tx
// (handling h=tx) reads its 4 gate-weights as one LDS.128. A reads are
// warp-uniform float4 broadcasts.
__global__ void k_final(const float* __restrict__ W, const float* __restrict__ bias,
                        const float* __restrict__ c_cur, float* __restrict__ out,
                        int out_size) {
    extern __shared__ float smem[];
    float*  sW  = smem;                       // 96*128 floats (permuted cols)
    float*  sB  = sW + 12288;                 // 128 floats (original layout)
    float4* sA4 = (float4*)(sB + 128);        // 64 rows * 24 float4

    int tid = threadIdx.x;
    int tx  = tid & 31;
    int ty  = tid >> 5;
    int row0 = blockIdx.x * 64;

    // load W with gate-interleave permutation: (k, c) -> sW[k*128 + (c&31)*4 + (c>>5)]
    const float4* W4 = (const float4*)W;
#pragma unroll
    for (int t = 0; t < 12; t++) {
        int f = tid + t * 256;                // < 3072
        int k = f >> 5;
        int c0 = (f & 31) * 4;
        float4 v = W4[f];
        float vv[4] = {v.x, v.y, v.z, v.w};
#pragma unroll
        for (int j = 0; j < 4; j++) {
            int c = c0 + j;
            sW[k * 128 + (c & 31) * 4 + (c >> 5)] = vv[j];
        }
    }
    if (tid < 32) ((float4*)sB)[tid] = ((const float4*)bias)[tid];

    // load A tile straight from finished g_vec
#pragma unroll
    for (int t = 0; t < 6; t++) {
        int f  = tid + t * 256;               // < 1536
        int grow = row0 + f / 24;
        sA4[f] = (grow < T2) ? g_vec[(long long)grow * 24 + (f % 24)]
                             : make_float4(0.f, 0.f, 0.f, 0.f);
    }
    __syncthreads();

    float4 acc[8];
#pragma unroll
    for (int i = 0; i < 8; i++) acc[i] = make_float4(0.f, 0.f, 0.f, 0.f);

    const float4* A4  = sA4 + (ty * 8) * 24;   // row stride: 24 float4
    const float4* W4s = (const float4*)sW;     // row k: 32 float4; thread uses [k*32+tx]

#pragma unroll 2
    for (int k4 = 0; k4 < 24; k4++) {
        float4 a[8];
#pragma unroll
        for (int i = 0; i < 8; i++) a[i] = A4[i * 24 + k4];  // warp-uniform broadcast
#pragma unroll
        for (int j = 0; j < 4; j++) {
            float4 w = W4s[(k4 * 4 + j) * 32 + tx];
#pragma unroll
            for (int i = 0; i < 8; i++) {
                float av = (j == 0) ? a[i].x : (j == 1) ? a[i].y : (j == 2) ? a[i].z : a[i].w;
                acc[i].x += av * w.x;
                acc[i].y += av * w.y;
                acc[i].z += av * w.z;
                acc[i].w += av * w.w;
            }
        }
    }

    float bi = sB[tx], bf = sB[32 + tx], bo = sB[64 + tx], bg = sB[96 + tx];
    bool write_c = (out_size >= 2 * BNH);

#pragma unroll
    for (int i = 0; i < 8; i++) {
        int grow = row0 + ty * 8 + i;
        if (grow < T2) {
            int n = grow >> 1, b = grow & 1;
            float ig = 1.f / (1.f + expf(-(acc[i].x + bi)));
            float fg = 1.f / (1.f + expf(-(acc[i].y + bf)));
            float og = 1.f / (1.f + expf(-(acc[i].z + bo)));
            float gg = tanhf(acc[i].w + bg);
            int off = (b * NN + n) * NH + tx;
            float cn = fg * c_cur[off] + ig * gg;
            out[off] = og * tanhf(cn);         // h_next
            if (write_c) out[BNH + off] = cn;  // c_next
        }
    }
}

// ---------------------------------------------------------------------------
extern "C" void kernel_launch(void* const* d_in, const int* in_sizes, int n_in,
                              void* d_out, int out_size) {
    const float* x    = (const float*)d_in[0];
    const void*  ei   = d_in[1];
    const float* h    = (const float*)d_in[2];
    const float* c    = (const float*)d_in[3];
    const float* W    = (const float*)d_in[4];
    const float* bias = (const float*)d_in[5];
    float*       out  = (float*)d_out;
    int E = in_sizes[1] / 2;   // element count -> E for either dtype

    k_detect<<<1, 256>>>(ei);
    k_zero<<<(NN + 255) / 256, 256>>>();
    k_deg<<<(E + 255) / 256, 256>>>(ei, E);
    k_scan<<<1, 1024>>>();
    k_scale<<<(NN * 48 + 255) / 256, 256>>>((const float4*)x, (const float4*)h);
    k_fill<<<(E + 255) / 256, 256>>>(ei, E);
    k_gather<<<(NN * 16 + 255) / 256, 256>>>();

    const int SMEM = (12288 + 128) * 4 + 64 * 24 * 16;  // 74240 B
    cudaFuncSetAttribute(k_final, cudaFuncAttributeMaxDynamicSharedMemorySize, SMEM);
    k_final<<<(T2 + 63) / 64, 256, SMEM>>>(W, bias, c, out, out_size);
}

// round 7
// speedup vs baseline: 1.1411x; 1.1411x over previous
#include <cuda_runtime.h>
#include <math.h>

// Problem constants (fixed by the dataset)
#define NB 2
#define NN 50000
#define NF 64
#define NH 32
#define FH 96              // F + H
#define T2 (NB * NN)       // 100000 task rows
#define BNH (NB * NN * NH) // 3,200,000 elements per output tensor
#define EMAX 1000000       // adjacency capacity (dataset E = 800000)
#define NBLK 196           // scan blocks: 196*256 = 50176 >= NN

// Scratch: static __device__ arrays (no runtime allocation allowed)
__device__ int    g_is64;           // 1 if edge_index is int64, 0 if int32
__device__ int    g_deg[NN];        // edge-only in-degree (no self loop)
__device__ int    g_bsum[NBLK];     // per-block degree sums
__device__ int    g_boff[NBLK];     // exclusive prefix of block sums
__device__ int    g_off[NN + 1];    // CSR offsets
__device__ int    g_cur[NN];        // CSR fill cursors
__device__ int    g_adj[EMAX];      // CSR: source node per incoming edge
__device__ float  g_dinv[NN];       // rsqrt(deg+1)
__device__ float4 g_y[NN * 48];     // per node: 48 float4 = [b=0: 24][b=1: 24]
__device__ float4 g_vec[NN * 48];   // finished GEMM input (dinv*(sum+self))

// ---------------------------------------------------------------------------
__device__ __forceinline__ int load_idx(const void* ei, long long pos, int is64) {
    if (is64) return (int)((const long long*)ei)[pos];
    return ((const int*)ei)[pos];
}

// K_detect: decide int64 vs int32 from the first 256 values.
__global__ void k_detect(const void* ei) {
    int t = threadIdx.x;
    if (t == 0) g_is64 = 1;
    __syncthreads();
    long long v = ((const long long*)ei)[t];
    if (v < 0 || v >= NN) atomicAnd(&g_is64, 0);
}

// K_zero: deg = 0
__global__ void k_zero() {
    int n = blockIdx.x * blockDim.x + threadIdx.x;
    if (n < NN) g_deg[n] = 0;
}

// K_deg: count edge targets
__global__ void k_deg(const void* __restrict__ ei, int E) {
    int e = blockIdx.x * blockDim.x + threadIdx.x;
    if (e >= E) return;
    int d = load_idx(ei, (long long)E + e, g_is64);
    if ((unsigned)d < NN) atomicAdd(&g_deg[d], 1);
}

// K_scanA: per-block reduction of deg -> g_bsum
__global__ void k_scanA() {
    __shared__ int sh[256];
    int tid = threadIdx.x;
    int n = blockIdx.x * 256 + tid;
    int v = (n < NN) ? g_deg[n] : 0;
    // warp reduce then cross-warp
    for (int o = 16; o > 0; o >>= 1) v += __shfl_down_sync(0xffffffffu, v, o);
    if ((tid & 31) == 0) sh[tid >> 5] = v;
    __syncthreads();
    if (tid < 8) {
        int s = sh[tid];
        for (int o = 4; o > 0; o >>= 1) s += __shfl_down_sync(0xffu, s, o);
        if (tid == 0) g_bsum[blockIdx.x] = s;
    }
}

// K_scanB: exclusive scan of NBLK block sums (single block, 256 threads)
__global__ void k_scanB() {
    __shared__ int sh[256];
    int tid = threadIdx.x;
    int v = (tid < NBLK) ? g_bsum[tid] : 0;
    sh[tid] = v;
    __syncthreads();
    for (int d = 1; d < 256; d <<= 1) {
        int u = (tid >= d) ? sh[tid - d] : 0;
        __syncthreads();
        sh[tid] += u;
        __syncthreads();
    }
    if (tid < NBLK) g_boff[tid] = sh[tid] - v;   // exclusive
    if (tid == NBLK - 1) g_off[NN] = sh[tid];    // total edge count
}

// K_scanC: intra-block scan + block offset -> g_off/g_cur/g_dinv
__global__ void k_scanC() {
    __shared__ int sh[256];
    int tid = threadIdx.x;
    int n = blockIdx.x * 256 + tid;
    int dg = (n < NN) ? g_deg[n] : 0;
    sh[tid] = dg;
    __syncthreads();
    for (int d = 1; d < 256; d <<= 1) {
        int u = (tid >= d) ? sh[tid - d] : 0;
        __syncthreads();
        sh[tid] += u;
        __syncthreads();
    }
    if (n < NN) {
        int off = g_boff[blockIdx.x] + sh[tid] - dg;  // exclusive
        g_off[n] = off;
        g_cur[n] = off;
        g_dinv[n] = rsqrtf((float)(dg + 1));
    }
}

// K_scale: y[n][b][:] = dinv[n] * concat(x[b][n], h[b][n])
__global__ void k_scale(const float4* __restrict__ x4, const float4* __restrict__ h4) {
    int i = blockIdx.x * blockDim.x + threadIdx.x;  // over NN*48 float4s
    if (i >= NN * 48) return;
    int n  = i / 48;
    int r  = i % 48;
    int b  = r / 24;
    int k4 = r % 24;
    float4 v;
    if (k4 < 16) v = x4[(b * NN + n) * 16 + k4];
    else         v = h4[(b * NN + n) * 8 + (k4 - 16)];
    float s = g_dinv[n];
    v.x *= s; v.y *= s; v.z *= s; v.w *= s;
    g_y[i] = v;
}

// K_fill: scatter edge sources into CSR slots (cheap int atomics)
__global__ void k_fill(const void* __restrict__ ei, int E) {
    int e = blockIdx.x * blockDim.x + threadIdx.x;
    if (e >= E) return;
    int is64 = g_is64;
    int s = load_idx(ei, e, is64);
    int d = load_idx(ei, (long long)E + e, is64);
    if ((unsigned)s >= NN || (unsigned)d >= NN) return;
    int pos = atomicAdd(&g_cur[d], 1);
    if (pos < EMAX) g_adj[pos] = s;
}

// ---------------------------------------------------------------------------
// K_gather: per node, HALF-WARP accumulates all incoming neighbors in
// registers (3 float4/lane = 192 floats per node, both batches), adds self,
// scales by dinv, writes the finished GEMM input. No float atomics.
__global__ void k_gather() {
    int g    = blockIdx.x * blockDim.x + threadIdx.x;
    int node = g >> 4;
    int lane = g & 15;
    if (node >= NN) return;
    const float4* ys = g_y + (long long)node * 48;
    float4 a0 = ys[lane];
    float4 a1 = ys[lane + 16];
    float4 a2 = ys[lane + 32];
    int beg = g_off[node], end = g_off[node + 1];
    for (int p = beg; p < end; p++) {
        int s = g_adj[p];
        const float4* yv = g_y + (long long)s * 48;
        float4 v0 = yv[lane], v1 = yv[lane + 16], v2 = yv[lane + 32];
        a0.x += v0.x; a0.y += v0.y; a0.z += v0.z; a0.w += v0.w;
        a1.x += v1.x; a1.y += v1.y; a1.z += v1.z; a1.w += v1.w;
        a2.x += v2.x; a2.y += v2.y; a2.z += v2.z; a2.w += v2.w;
    }
    float dv = g_dinv[node];
    a0.x *= dv; a0.y *= dv; a0.z *= dv; a0.w *= dv;
    a1.x *= dv; a1.y *= dv; a1.z *= dv; a1.w *= dv;
    a2.x *= dv; a2.y *= dv; a2.z *= dv; a2.w *= dv;
    float4* out = g_vec + (long long)node * 48;
    out[lane]      = a0;
    out[lane + 16] = a1;
    out[lane + 32] = a2;
}

// ---------------------------------------------------------------------------
// K_final: conv = vec@W + b; LSTM gates; store h,c.
// W in smem gate-interleaved (col' = h*4+gate): one LDS.128 per thread per
// (k,j); A reads are warp-uniform float4 broadcasts.
__global__ void k_final(const float* __restrict__ W, const float* __restrict__ bias,
                        const float* __restrict__ c_cur, float* __restrict__ out,
                        int out_size) {
    extern __shared__ float smem[];
    float*  sW  = smem;                       // 96*128 floats (permuted cols)
    float*  sB  = sW + 12288;                 // 128 floats (original layout)
    float4* sA4 = (float4*)(sB + 128);        // 64 rows * 24 float4

    int tid = threadIdx.x;
    int tx  = tid & 31;
    int ty  = tid >> 5;
    int row0 = blockIdx.x * 64;

    // load W with gate-interleave permutation: (k, c) -> sW[k*128 + (c&31)*4 + (c>>5)]
    const float4* W4 = (const float4*)W;
#pragma unroll
    for (int t = 0; t < 12; t++) {
        int f = tid + t * 256;                // < 3072
        int k = f >> 5;
        int c0 = (f & 31) * 4;
        float4 v = W4[f];
        float vv[4] = {v.x, v.y, v.z, v.w};
#pragma unroll
        for (int j = 0; j < 4; j++) {
            int c = c0 + j;
            sW[k * 128 + (c & 31) * 4 + (c >> 5)] = vv[j];
        }
    }
    if (tid < 32) ((float4*)sB)[tid] = ((const float4*)bias)[tid];

    // load A tile straight from finished g_vec
#pragma unroll
    for (int t = 0; t < 6; t++) {
        int f  = tid + t * 256;               // < 1536
        int grow = row0 + f / 24;
        sA4[f] = (grow < T2) ? g_vec[(long long)grow * 24 + (f % 24)]
                             : make_float4(0.f, 0.f, 0.f, 0.f);
    }
    __syncthreads();

    float4 acc[8];
#pragma unroll
    for (int i = 0; i < 8; i++) acc[i] = make_float4(0.f, 0.f, 0.f, 0.f);

    const float4* A4  = sA4 + (ty * 8) * 24;   // row stride: 24 float4
    const float4* W4s = (const float4*)sW;     // row k: 32 float4; thread uses [k*32+tx]

#pragma unroll 2
    for (int k4 = 0; k4 < 24; k4++) {
        float4 a[8];
#pragma unroll
        for (int i = 0; i < 8; i++) a[i] = A4[i * 24 + k4];  // warp-uniform broadcast
#pragma unroll
        for (int j = 0; j < 4; j++) {
            float4 w = W4s[(k4 * 4 + j) * 32 + tx];
#pragma unroll
            for (int i = 0; i < 8; i++) {
                float av = (j == 0) ? a[i].x : (j == 1) ? a[i].y : (j == 2) ? a[i].z : a[i].w;
                acc[i].x += av * w.x;
                acc[i].y += av * w.y;
                acc[i].z += av * w.z;
                acc[i].w += av * w.w;
            }
        }
    }

    float bi = sB[tx], bf = sB[32 + tx], bo = sB[64 + tx], bg = sB[96 + tx];
    bool write_c = (out_size >= 2 * BNH);

#pragma unroll
    for (int i = 0; i < 8; i++) {
        int grow = row0 + ty * 8 + i;
        if (grow < T2) {
            int n = grow >> 1, b = grow & 1;
            float ig = 1.f / (1.f + expf(-(acc[i].x + bi)));
            float fg = 1.f / (1.f + expf(-(acc[i].y + bf)));
            float og = 1.f / (1.f + expf(-(acc[i].z + bo)));
            float gg = tanhf(acc[i].w + bg);
            int off = (b * NN + n) * NH + tx;
            float cn = fg * c_cur[off] + ig * gg;
            out[off] = og * tanhf(cn);         // h_next
            if (write_c) out[BNH + off] = cn;  // c_next
        }
    }
}

// ---------------------------------------------------------------------------
extern "C" void kernel_launch(void* const* d_in, const int* in_sizes, int n_in,
                              void* d_out, int out_size) {
    const float* x    = (const float*)d_in[0];
    const void*  ei   = d_in[1];
    const float* h    = (const float*)d_in[2];
    const float* c    = (const float*)d_in[3];
    const float* W    = (const float*)d_in[4];
    const float* bias = (const float*)d_in[5];
    float*       out  = (float*)d_out;
    int E = in_sizes[1] / 2;   // element count -> E for either dtype

    k_detect<<<1, 256>>>(ei);
    k_zero<<<(NN + 255) / 256, 256>>>();
    k_deg<<<(E + 255) / 256, 256>>>(ei, E);
    k_scanA<<<NBLK, 256>>>();
    k_scanB<<<1, 256>>>();
    k_scanC<<<NBLK, 256>>>();
    k_scale<<<(NN * 48 + 255) / 256, 256>>>((const float4*)x, (const float4*)h);
    k_fill<<<(E + 255) / 256, 256>>>(ei, E);
    k_gather<<<(NN * 16 + 255) / 256, 256>>>();

    const int SMEM = (12288 + 128) * 4 + 64 * 24 * 16;  // 74240 B
    cudaFuncSetAttribute(k_final, cudaFuncAttributeMaxDynamicSharedMemorySize, SMEM);
    k_final<<<(T2 + 63) / 64, 256, SMEM>>>(W, bias, c, out, out_size);
}

// round 8
// speedup vs baseline: 1.6489x; 1.4450x over previous
#include <cuda_runtime.h>
#include <math.h>

// Problem constants (fixed by the dataset)
#define NB 2
#define NN 50000
#define NF 64
#define NH 32
#define FH 96              // F + H
#define T2 (NB * NN)       // 100000 task rows
#define BNH (NB * NN * NH) // 3,200,000 elements per output tensor
#define EMAX 1000000       // adjacency capacity (dataset E = 800000)
#define NBLK 196           // scan blocks: 196*256 = 50176 >= NN

// Scratch
__device__ int    g_is64;
__device__ int    g_deg[NN];
__device__ int    g_bsum[NBLK];
__device__ int    g_boff[NBLK];
__device__ int    g_off[NN + 1];
__device__ int    g_cur[NN];
__device__ int    g_adj[EMAX];
__device__ float  g_dinv[NN];       // rsqrt(deg+1)

// ---------------------------------------------------------------------------
__device__ __forceinline__ int load_idx(const void* ei, long long pos, int is64) {
    if (is64) return (int)((const long long*)ei)[pos];
    return ((const int*)ei)[pos];
}

// K_detect+zero: block 0 detects dtype; all blocks zero deg.
__global__ void k_init(const void* ei) {
    int tid = threadIdx.x;
    int n = blockIdx.x * 256 + tid;
    if (n < NN) g_deg[n] = 0;
    if (blockIdx.x == 0) {
        if (tid == 0) g_is64 = 1;
        __syncthreads();
        long long v = ((const long long*)ei)[tid];
        if (v < 0 || v >= NN) atomicAnd(&g_is64, 0);
    }
}

// K_deg: count edge targets
__global__ void k_deg(const void* __restrict__ ei, int E) {
    int e = blockIdx.x * blockDim.x + threadIdx.x;
    if (e >= E) return;
    int d = load_idx(ei, (long long)E + e, g_is64);
    if ((unsigned)d < NN) atomicAdd(&g_deg[d], 1);
}

// K_scanA: per-block reduction of deg -> g_bsum
__global__ void k_scanA() {
    __shared__ int sh[8];
    int tid = threadIdx.x;
    int n = blockIdx.x * 256 + tid;
    int v = (n < NN) ? g_deg[n] : 0;
    for (int o = 16; o > 0; o >>= 1) v += __shfl_down_sync(0xffffffffu, v, o);
    if ((tid & 31) == 0) sh[tid >> 5] = v;
    __syncthreads();
    if (tid < 8) {
        int s = sh[tid];
        for (int o = 4; o > 0; o >>= 1) s += __shfl_down_sync(0xffu, s, o);
        if (tid == 0) g_bsum[blockIdx.x] = s;
    }
}

// K_scanB: exclusive scan of NBLK block sums (single block)
__global__ void k_scanB() {
    __shared__ int sh[256];
    int tid = threadIdx.x;
    int v = (tid < NBLK) ? g_bsum[tid] : 0;
    sh[tid] = v;
    __syncthreads();
    for (int d = 1; d < 256; d <<= 1) {
        int u = (tid >= d) ? sh[tid - d] : 0;
        __syncthreads();
        sh[tid] += u;
        __syncthreads();
    }
    if (tid < NBLK) g_boff[tid] = sh[tid] - v;
    if (tid == NBLK - 1) g_off[NN] = sh[tid];
}

// K_scanC: intra-block scan + block offset -> g_off/g_cur/g_dinv
__global__ void k_scanC() {
    __shared__ int sh[256];
    int tid = threadIdx.x;
    int n = blockIdx.x * 256 + tid;
    int dg = (n < NN) ? g_deg[n] : 0;
    sh[tid] = dg;
    __syncthreads();
    for (int d = 1; d < 256; d <<= 1) {
        int u = (tid >= d) ? sh[tid - d] : 0;
        __syncthreads();
        sh[tid] += u;
        __syncthreads();
    }
    if (n < NN) {
        int off = g_boff[blockIdx.x] + sh[tid] - dg;
        g_off[n] = off;
        g_cur[n] = off;
        g_dinv[n] = rsqrtf((float)(dg + 1));
    }
}

// K_fill: scatter edge sources into CSR slots
__global__ void k_fill(const void* __restrict__ ei, int E) {
    int e = blockIdx.x * blockDim.x + threadIdx.x;
    if (e >= E) return;
    int is64 = g_is64;
    int s = load_idx(ei, e, is64);
    int d = load_idx(ei, (long long)E + e, is64);
    if ((unsigned)s >= NN || (unsigned)d >= NN) return;
    int pos = atomicAdd(&g_cur[d], 1);
    if (pos < EMAX) g_adj[pos] = s;
}

// ---------------------------------------------------------------------------
// Per-lane feature fetch: column c in [0,48) of node n's concatenated
// [b0: x(16 f4) h(8 f4)][b1: x(16 f4) h(8 f4)] row, straight from inputs.
__device__ __forceinline__ float4 load_feat(const float4* __restrict__ x4,
                                            const float4* __restrict__ h4,
                                            int n, int c) {
    int b  = (c >= 24) ? 1 : 0;
    int k4 = c - 24 * b;
    if (k4 < 16) return x4[((long long)b * NN + n) * 16 + k4];
    return h4[((long long)b * NN + n) * 8 + (k4 - 16)];
}

// K_final: fused gather + GEMM + LSTM.
// Gather phase: half-warp per node (2 nodes each), accumulate dinv[s]-scaled
// neighbor features + self in registers, scale by dinv[node], write smem A.
// GEMM phase: W gate-interleaved in smem, A warp-uniform broadcasts.
__global__ void k_final(const float4* __restrict__ x4, const float4* __restrict__ h4,
                        const float* __restrict__ W, const float* __restrict__ bias,
                        const float* __restrict__ c_cur, float* __restrict__ out,
                        int out_size) {
    extern __shared__ float smem[];
    float*  sW  = smem;                       // 96*128 floats (permuted cols)
    float*  sB  = sW + 12288;                 // 128 floats
    float4* sA4 = (float4*)(sB + 128);        // 64 rows * 24 float4

    int tid = threadIdx.x;
    int tx  = tid & 31;
    int ty  = tid >> 5;
    int row0  = blockIdx.x * 64;
    int node0 = row0 >> 1;

    // load W with gate-interleave permutation: (k,c) -> sW[k*128 + (c&31)*4 + (c>>5)]
    const float4* W4 = (const float4*)W;
#pragma unroll
    for (int t = 0; t < 12; t++) {
        int f = tid + t * 256;                // < 3072
        int k = f >> 5;
        int c0 = (f & 31) * 4;
        float4 v = W4[f];
        float vv[4] = {v.x, v.y, v.z, v.w};
#pragma unroll
        for (int j = 0; j < 4; j++) {
            int c = c0 + j;
            sW[k * 128 + (c & 31) * 4 + (c >> 5)] = vv[j];
        }
    }
    if (tid < 32) ((float4*)sB)[tid] = ((const float4*)bias)[tid];

    // ---- gather phase: 16 half-warps, 32 nodes -> 2 nodes each ----
    {
        int hw   = tid >> 4;
        int lane = tid & 15;
        int c0 = lane, c1 = lane + 16, c2 = lane + 32;
        for (int nn = hw; nn < 32; nn += 16) {
            int node = node0 + nn;
            float4 a0 = make_float4(0.f, 0.f, 0.f, 0.f);
            float4 a1 = a0, a2 = a0;
            if (node < NN) {
                float dn = g_dinv[node];
                // self term (coefficient dinv[n]^2; one dn here, one at the end)
                float4 v0 = load_feat(x4, h4, node, c0);
                float4 v1 = load_feat(x4, h4, node, c1);
                float4 v2 = load_feat(x4, h4, node, c2);
                a0.x = dn * v0.x; a0.y = dn * v0.y; a0.z = dn * v0.z; a0.w = dn * v0.w;
                a1.x = dn * v1.x; a1.y = dn * v1.y; a1.z = dn * v1.z; a1.w = dn * v1.w;
                a2.x = dn * v2.x; a2.y = dn * v2.y; a2.z = dn * v2.z; a2.w = dn * v2.w;
                int beg = g_off[node], end = g_off[node + 1];
                for (int p = beg; p < end; p++) {
                    int s = g_adj[p];
                    float dv = g_dinv[s];
                    float4 w0 = load_feat(x4, h4, s, c0);
                    float4 w1 = load_feat(x4, h4, s, c1);
                    float4 w2 = load_feat(x4, h4, s, c2);
                    a0.x += dv * w0.x; a0.y += dv * w0.y; a0.z += dv * w0.z; a0.w += dv * w0.w;
                    a1.x += dv * w1.x; a1.y += dv * w1.y; a1.z += dv * w1.z; a1.w += dv * w1.w;
                    a2.x += dv * w2.x; a2.y += dv * w2.y; a2.z += dv * w2.z; a2.w += dv * w2.w;
                }
                a0.x *= dn; a0.y *= dn; a0.z *= dn; a0.w *= dn;
                a1.x *= dn; a1.y *= dn; a1.z *= dn; a1.w *= dn;
                a2.x *= dn; a2.y *= dn; a2.z *= dn; a2.w *= dn;
            }
            // write: column c -> (b = c>=24, k4 = c-24b), row r = nn*2 + b
#pragma unroll
            for (int t = 0; t < 3; t++) {
                int c = c0 + 16 * t;
                float4 av = (t == 0) ? a0 : (t == 1) ? a1 : a2;
                int b  = (c >= 24) ? 1 : 0;
                int k4 = c - 24 * b;
                sA4[(nn * 2 + b) * 24 + k4] = av;
            }
        }
    }
    __syncthreads();

    // ---- GEMM phase ----
    float4 acc[8];
#pragma unroll
    for (int i = 0; i < 8; i++) acc[i] = make_float4(0.f, 0.f, 0.f, 0.f);

    const float4* A4  = sA4 + (ty * 8) * 24;
    const float4* W4s = (const float4*)sW;

#pragma unroll 2
    for (int k4 = 0; k4 < 24; k4++) {
        float4 a[8];
#pragma unroll
        for (int i = 0; i < 8; i++) a[i] = A4[i * 24 + k4];
#pragma unroll
        for (int j = 0; j < 4; j++) {
            float4 w = W4s[(k4 * 4 + j) * 32 + tx];
#pragma unroll
            for (int i = 0; i < 8; i++) {
                float av = (j == 0) ? a[i].x : (j == 1) ? a[i].y : (j == 2) ? a[i].z : a[i].w;
                acc[i].x += av * w.x;
                acc[i].y += av * w.y;
                acc[i].z += av * w.z;
                acc[i].w += av * w.w;
            }
        }
    }

    float bi = sB[tx], bf = sB[32 + tx], bo = sB[64 + tx], bg = sB[96 + tx];
    bool write_c = (out_size >= 2 * BNH);

#pragma unroll
    for (int i = 0; i < 8; i++) {
        int grow = row0 + ty * 8 + i;
        if (grow < T2) {
            int n = grow >> 1, b = grow & 1;
            float ig = 1.f / (1.f + expf(-(acc[i].x + bi)));
            float fg = 1.f / (1.f + expf(-(acc[i].y + bf)));
            float og = 1.f / (1.f + expf(-(acc[i].z + bo)));
            float gg = tanhf(acc[i].w + bg);
            int off = (b * NN + n) * NH + tx;
            float cn = fg * c_cur[off] + ig * gg;
            out[off] = og * tanhf(cn);         // h_next
            if (write_c) out[BNH + off] = cn;  // c_next
        }
    }
}

// ---------------------------------------------------------------------------
extern "C" void kernel_launch(void* const* d_in, const int* in_sizes, int n_in,
                              void* d_out, int out_size) {
    const float* x    = (const float*)d_in[0];
    const void*  ei   = d_in[1];
    const float* h    = (const float*)d_in[2];
    const float* c    = (const float*)d_in[3];
    const float* W    = (const float*)d_in[4];
    const float* bias = (const float*)d_in[5];
    float*       out  = (float*)d_out;
    int E = in_sizes[1] / 2;

    k_init<<<NBLK, 256>>>(ei);
    k_deg<<<(E + 255) / 256, 256>>>(ei, E);
    k_scanA<<<NBLK, 256>>>();
    k_scanB<<<1, 256>>>();
    k_scanC<<<NBLK, 256>>>();
    k_fill<<<(E + 255) / 256, 256>>>(ei, E);

    const int SMEM = (12288 + 128) * 4 + 64 * 24 * 16;  // 74240 B
    cudaFuncSetAttribute(k_final, cudaFuncAttributeMaxDynamicSharedMemorySize, SMEM);
    k_final<<<(T2 + 63) / 64, 256, SMEM>>>((const float4*)x, (const float4*)h,
                                           W, bias, c, out, out_size);
}